// round 5
// baseline (speedup 1.0000x reference)
#include <cuda_runtime.h>
#include <math.h>

#define BB 16
#define TT 16
#define LL 128
#define XX 256
#define HH 512
#define YY 256
#define RCTA 8
#define TPB 512

__device__ __align__(16) float g_w1[BB * HH * XX];
__device__ __align__(16) float g_w2[BB * HH * HH];
__device__ __align__(16) float g_w3[BB * HH * HH];
__device__ __align__(16) float g_w4[BB * YY * HH];
__device__ __align__(16) float g_b1[BB * HH];
__device__ __align__(16) float g_b2[BB * HH];
__device__ __align__(16) float g_b3[BB * HH];
__device__ __align__(16) float g_w2T[HH * HH];
__device__ __align__(16) float g_w3T[HH * HH];
__device__ __align__(16) float g_w4T[HH * YY];
__device__ __align__(16) float g_h1A[BB * TT * HH];
__device__ __align__(16) float g_h2A[BB * TT * HH];
__device__ __align__(16) float g_h3A[BB * TT * HH];
__device__ __align__(16) float g_hgA[BB * TT * HH];
__device__ __align__(16) float g_dz1A[BB * TT * HH];
__device__ __align__(16) float g_dz2A[BB * TT * HH];
__device__ __align__(16) float g_dz3A[BB * TT * HH];
__device__ __align__(16) float g_dlA[BB * TT * YY];
__device__ __align__(16) float g_xg[BB * TT * TT];
__device__ __align__(16) float g_ea[BB * LL * HH];
__device__ __align__(16) float g_eb[BB * LL * HH];

__device__ __forceinline__ float warp_sum(float v) {
    v += __shfl_xor_sync(0xffffffffu, v, 16);
    v += __shfl_xor_sync(0xffffffffu, v, 8);
    v += __shfl_xor_sync(0xffffffffu, v, 4);
    v += __shfl_xor_sync(0xffffffffu, v, 2);
    v += __shfl_xor_sync(0xffffffffu, v, 1);
    return v;
}

// packed fp32x2 FMA: d += a*b (componentwise), full fp32 precision, 2x FFMA rate
__device__ __forceinline__ void ffma2(float2& d, float2 a, float2 b) {
    asm("{\n\t"
        ".reg .b64 ra, rb, rd;\n\t"
        "mov.b64 ra, {%2, %3};\n\t"
        "mov.b64 rb, {%4, %5};\n\t"
        "mov.b64 rd, {%0, %1};\n\t"
        "fma.rn.f32x2 rd, ra, rb, rd;\n\t"
        "mov.b64 {%0, %1}, rd;\n\t"
        "}" : "+f"(d.x), "+f"(d.y) : "f"(a.x), "f"(a.y), "f"(b.x), "f"(b.y));
}

__device__ __forceinline__ void csync() {
    asm volatile("barrier.cluster.arrive.aligned;" ::: "memory");
    asm volatile("barrier.cluster.wait.aligned;" ::: "memory");
}

// ---------------- pre-pass: transposes ----------------
__global__ void __launch_bounds__(256) k_tr(const float* __restrict__ fc2,
                                            const float* __restrict__ fc3,
                                            const float* __restrict__ fc4) {
    __shared__ float tile[32][33];
    int bid = blockIdx.x;
    const float* src;
    float* dst;
    int RS, CS;
    if (bid < 256) { src = fc2; dst = g_w2T; RS = HH; CS = HH; }
    else if (bid < 512) { src = fc3; dst = g_w3T; bid -= 256; RS = HH; CS = HH; }
    else { src = fc4; dst = g_w4T; bid -= 512; RS = YY; CS = HH; }
    int tpr = CS / 32;
    int r0 = (bid / tpr) * 32, c0 = (bid % tpr) * 32;
    int tx = threadIdx.x & 31, ty = threadIdx.x >> 5;
    for (int i = ty; i < 32; i += 8) tile[i][tx] = src[(size_t)(r0 + i) * CS + c0 + tx];
    __syncthreads();
    for (int i = ty; i < 32; i += 8) dst[(size_t)(c0 + i) * RS + r0 + tx] = tile[tx][i];
}

__global__ void __launch_bounds__(256) k_miscA(const float* __restrict__ b1,
                                               const float* __restrict__ b2,
                                               const float* __restrict__ b3) {
    int gt = blockIdx.x * blockDim.x + threadIdx.x;
    int NT = gridDim.x * blockDim.x;
    for (int i = gt; i < BB * HH; i += NT) {
        int k = i & (HH - 1);
        g_b1[i] = b1[k]; g_b2[i] = b2[k]; g_b3[i] = b3[k];
    }
}

__global__ void __launch_bounds__(256) k_miscB(const float* __restrict__ tx) {
    int gt = blockIdx.x * blockDim.x + threadIdx.x;
    int NT = gridDim.x * blockDim.x;
    int gw = gt >> 5, lane = gt & 31;
    for (int d = gw; d < BB * TT * TT; d += NT >> 5) {
        int b = d >> 8, s1 = (d >> 4) & 15, s2 = d & 15;
        const float4* xa = (const float4*)(tx + (size_t)(b * TT + s1) * XX);
        const float4* xb = (const float4*)(tx + (size_t)(b * TT + s2) * XX);
        float4 a = xa[lane], c = xb[lane];
        float acc = a.x * c.x + a.y * c.y + a.z * c.z + a.w * c.w;
        a = xa[lane + 32]; c = xb[lane + 32];
        acc += a.x * c.x + a.y * c.y + a.z * c.z + a.w * c.w;
        acc = warp_sum(acc);
        if (lane == 0) g_xg[d] = acc;
    }
}

// octet matvec, packed 2 examples, fully unrolled (MLP=K/32)
template <int K>
__device__ __forceinline__ void omv2(const float* __restrict__ W, int n,
                                     const float2* s_xi, int l8, float2& acc) {
    const float4* w4 = (const float4*)(W + (size_t)n * K);
    const float4* xi4 = (const float4*)s_xi;
    acc = make_float2(0.f, 0.f);
#pragma unroll
    for (int jj = 0; jj < K / 32; jj++) {
        int j = l8 + jj * 8;
        float4 w = w4[j];
        float4 q0 = xi4[2 * j];
        float4 q1 = xi4[2 * j + 1];
        ffma2(acc, make_float2(w.x, w.x), make_float2(q0.x, q0.y));
        ffma2(acc, make_float2(w.y, w.y), make_float2(q0.z, q0.w));
        ffma2(acc, make_float2(w.z, w.z), make_float2(q1.x, q1.y));
        ffma2(acc, make_float2(w.w, w.w), make_float2(q1.z, q1.w));
    }
}

__device__ __forceinline__ void ored2(float2& a) {
#pragma unroll
    for (int m = 1; m < 8; m <<= 1) {
        a.x += __shfl_xor_sync(0xffffffffu, a.x, m);
        a.y += __shfl_xor_sync(0xffffffffu, a.y, m);
    }
}

template <int NOUT>
__device__ __forceinline__ void corr2(const float* __restrict__ uA, int b0, int n,
                                      const float* s_c, int t, int l8, float2& acc) {
#pragma unroll
    for (int ss = 0; ss < 2; ss++) {
        int s = l8 + ss * 8;
        if (s < t) {
            float u0 = __ldcg(uA + (size_t)(b0 * TT + s) * NOUT + n);
            float u1 = __ldcg(uA + (size_t)((b0 + 1) * TT + s) * NOUT + n);
            float2 c = *(const float2*)&s_c[2 * s];
            acc.x = fmaf(-c.x, u0, acc.x);
            acc.y = fmaf(-c.y, u1, acc.y);
        }
    }
}

template <int K>
__device__ __forceinline__ void stage(const float* __restrict__ curA, float2* s_xi,
                                      float* s_c, int b0, int t, int tid, float lr) {
    const float* r0 = curA + (size_t)(b0 * TT + t) * K;
    const float* r1 = curA + (size_t)((b0 + 1) * TT + t) * K;
    for (int k = tid; k < K; k += TPB)
        s_xi[k] = make_float2(__ldcg(r0 + k), __ldcg(r1 + k));
    __syncthreads();
    int wid = tid >> 5, lane = tid & 31;
    const float* sf = (const float*)s_xi;
    for (int p = wid; p < 2 * t; p += TPB / 32) {
        int b = p & 1, s = p >> 1;
        const float4* v4 = (const float4*)(curA + (size_t)((b0 + b) * TT + s) * K);
        float acc = 0.f;
#pragma unroll
        for (int j = lane, it = 0; it < K / 128; it++, j += 32) {
            float4 v = __ldcg(v4 + j);
            acc += v.x * sf[8 * j + b] + v.y * sf[8 * j + 2 + b]
                 + v.z * sf[8 * j + 4 + b] + v.w * sf[8 * j + 6 + b];
        }
        acc = warp_sum(acc);
        if (lane == 0) s_c[2 * s + b] = lr * acc;
    }
    __syncthreads();
}

// ---------------- training: 8 clusters x 8 CTAs, 2 examples/cluster ----------
__global__ void __cluster_dims__(RCTA, 1, 1) __launch_bounds__(TPB, 1)
k_train(const float* __restrict__ tx, const float* __restrict__ ty,
        const float* __restrict__ tg,
        const float* __restrict__ fc1, const float* __restrict__ fc2,
        const float* __restrict__ fc3, const float* __restrict__ fc4,
        const float* __restrict__ loglr) {
    __shared__ __align__(16) float2 s_xi[HH];
    __shared__ float s_c[32];
    int tid = threadIdx.x;
    int r = blockIdx.x & (RCTA - 1);
    int b0 = (blockIdx.x / RCTA) * 2;
    int l8 = tid & 7;
    int oct = tid >> 3;
    float lr = expf(*loglr);

    for (int t = 0; t < TT; t++) {
        // ---- fwd1 ----
        csync();
        {
            const float* r0 = tx + (size_t)(b0 * TT + t) * XX;
            const float* r1 = tx + (size_t)((b0 + 1) * TT + t) * XX;
            for (int k = tid; k < XX; k += TPB)
                s_xi[k] = make_float2(r0[k], r1[k]);
            if (tid < 32) {
                int s = tid >> 1, b = tid & 1;
                s_c[tid] = (s < t) ? lr * g_xg[((b0 + b) * TT + s) * TT + t] : 0.f;
            }
            __syncthreads();
            int n = r * 64 + oct;
            float2 a;
            omv2<XX>(fc1, n, s_xi, l8, a);
            corr2<HH>(g_dz1A, b0, n, s_c, t, l8, a);
            ored2(a);
            if (l8 == 0) {
                g_h1A[(size_t)(b0 * TT + t) * HH + n] = fmaxf(a.x + g_b1[b0 * HH + n], 0.f);
                g_h1A[(size_t)((b0 + 1) * TT + t) * HH + n] = fmaxf(a.y + g_b1[(b0 + 1) * HH + n], 0.f);
            }
        }
        // ---- fwd2 ----
        csync();
        stage<HH>(g_h1A, s_xi, s_c, b0, t, tid, lr);
        {
            int n = r * 64 + oct;
            float2 a;
            omv2<HH>(fc2, n, s_xi, l8, a);
            corr2<HH>(g_dz2A, b0, n, s_c, t, l8, a);
            ored2(a);
            if (l8 == 0) {
                g_h2A[(size_t)(b0 * TT + t) * HH + n] = fmaxf(a.x + g_b2[b0 * HH + n], 0.f);
                g_h2A[(size_t)((b0 + 1) * TT + t) * HH + n] = fmaxf(a.y + g_b2[(b0 + 1) * HH + n], 0.f);
            }
        }
        // ---- fwd3 + gate ----
        csync();
        stage<HH>(g_h2A, s_xi, s_c, b0, t, tid, lr);
        {
            int n = r * 64 + oct;
            float2 a;
            omv2<HH>(fc3, n, s_xi, l8, a);
            corr2<HH>(g_dz3A, b0, n, s_c, t, l8, a);
            ored2(a);
            if (l8 == 0) {
                float h30 = fmaxf(a.x + g_b3[b0 * HH + n], 0.f);
                float h31 = fmaxf(a.y + g_b3[(b0 + 1) * HH + n], 0.f);
                g_h3A[(size_t)(b0 * TT + t) * HH + n] = h30;
                g_h3A[(size_t)((b0 + 1) * TT + t) * HH + n] = h31;
                g_hgA[(size_t)(b0 * TT + t) * HH + n] = h30 * tg[(size_t)(b0 * TT + t) * HH + n];
                g_hgA[(size_t)((b0 + 1) * TT + t) * HH + n] = h31 * tg[(size_t)((b0 + 1) * TT + t) * HH + n];
            }
        }
        // ---- fwd4 -> dlogit ----
        csync();
        stage<HH>(g_hgA, s_xi, s_c, b0, t, tid, lr);
        if (oct < 32) {
            int n = r * 32 + oct;
            float2 a;
            omv2<HH>(fc4, n, s_xi, l8, a);
            corr2<YY>(g_dlA, b0, n, s_c, t, l8, a);
            ored2(a);
            if (l8 == 0) {
                g_dlA[(size_t)(b0 * TT + t) * YY + n] =
                    (2.f / (float)YY) * (a.x - ty[(size_t)(b0 * TT + t) * YY + n]);
                g_dlA[(size_t)((b0 + 1) * TT + t) * YY + n] =
                    (2.f / (float)YY) * (a.y - ty[(size_t)((b0 + 1) * TT + t) * YY + n]);
            }
        }
        // ---- bwd4 ----
        csync();
        stage<YY>(g_dlA, s_xi, s_c, b0, t, tid, lr);
        {
            int n = r * 64 + oct;
            float2 a;
            omv2<YY>(g_w4T, n, s_xi, l8, a);
            corr2<HH>(g_hgA, b0, n, s_c, t, l8, a);
            ored2(a);
            if (l8 == 0) {
                float h30 = g_h3A[(size_t)(b0 * TT + t) * HH + n];
                float h31 = g_h3A[(size_t)((b0 + 1) * TT + t) * HH + n];
                float d0 = (h30 > 0.f) ? a.x * tg[(size_t)(b0 * TT + t) * HH + n] : 0.f;
                float d1 = (h31 > 0.f) ? a.y * tg[(size_t)((b0 + 1) * TT + t) * HH + n] : 0.f;
                g_dz3A[(size_t)(b0 * TT + t) * HH + n] = d0;
                g_dz3A[(size_t)((b0 + 1) * TT + t) * HH + n] = d1;
                g_b3[b0 * HH + n] -= lr * d0;
                g_b3[(b0 + 1) * HH + n] -= lr * d1;
            }
        }
        // ---- bwd3 ----
        csync();
        stage<HH>(g_dz3A, s_xi, s_c, b0, t, tid, lr);
        {
            int n = r * 64 + oct;
            float2 a;
            omv2<HH>(g_w3T, n, s_xi, l8, a);
            corr2<HH>(g_h2A, b0, n, s_c, t, l8, a);
            ored2(a);
            if (l8 == 0) {
                float h20 = g_h2A[(size_t)(b0 * TT + t) * HH + n];
                float h21 = g_h2A[(size_t)((b0 + 1) * TT + t) * HH + n];
                float d0 = (h20 > 0.f) ? a.x : 0.f;
                float d1 = (h21 > 0.f) ? a.y : 0.f;
                g_dz2A[(size_t)(b0 * TT + t) * HH + n] = d0;
                g_dz2A[(size_t)((b0 + 1) * TT + t) * HH + n] = d1;
                g_b2[b0 * HH + n] -= lr * d0;
                g_b2[(b0 + 1) * HH + n] -= lr * d1;
            }
        }
        // ---- bwd2 ----
        csync();
        stage<HH>(g_dz2A, s_xi, s_c, b0, t, tid, lr);
        {
            int n = r * 64 + oct;
            float2 a;
            omv2<HH>(g_w2T, n, s_xi, l8, a);
            corr2<HH>(g_h1A, b0, n, s_c, t, l8, a);
            ored2(a);
            if (l8 == 0) {
                float h10 = g_h1A[(size_t)(b0 * TT + t) * HH + n];
                float h11 = g_h1A[(size_t)((b0 + 1) * TT + t) * HH + n];
                float d0 = (h10 > 0.f) ? a.x : 0.f;
                float d1 = (h11 > 0.f) ? a.y : 0.f;
                g_dz1A[(size_t)(b0 * TT + t) * HH + n] = d0;
                g_dz1A[(size_t)((b0 + 1) * TT + t) * HH + n] = d1;
                g_b1[b0 * HH + n] -= lr * d0;
                g_b1[(b0 + 1) * HH + n] -= lr * d1;
            }
        }
    }
}

// ---------------- materialize: warp-per-row rank-16 --------------------------
__global__ void __launch_bounds__(256) k_material(
    const float* __restrict__ fc1, const float* __restrict__ fc2,
    const float* __restrict__ fc3, const float* __restrict__ fc4,
    const float* __restrict__ tx, const float* __restrict__ loglr) {
    float lr = expf(*loglr);
    int gw = (blockIdx.x * blockDim.x + threadIdx.x) >> 5;
    int lane = threadIdx.x & 31;
    int NW = (gridDim.x * blockDim.x) >> 5;
    // w1: rows BB*HH, K=256 (64 f4)
    for (int row = gw; row < BB * HH; row += NW) {
        int b = row >> 9, n = row & 511;
        float uval = (lane < TT) ? lr * g_dz1A[(size_t)(b * TT + lane) * HH + n] : 0.f;
#pragma unroll
        for (int it = 0; it < 2; it++) {
            int k4 = lane + it * 32;
            float4 acc = ((const float4*)fc1)[n * 64 + k4];
#pragma unroll
            for (int s = 0; s < TT; s++) {
                float u = __shfl_sync(0xffffffffu, uval, s);
                float4 v = ((const float4*)tx)[(b * TT + s) * 64 + k4];
                acc.x -= u * v.x; acc.y -= u * v.y; acc.z -= u * v.z; acc.w -= u * v.w;
            }
            ((float4*)g_w1)[(size_t)row * 64 + k4] = acc;
        }
    }
    // w2
    for (int row = gw; row < BB * HH; row += NW) {
        int b = row >> 9, n = row & 511;
        float uval = (lane < TT) ? lr * g_dz2A[(size_t)(b * TT + lane) * HH + n] : 0.f;
#pragma unroll
        for (int it = 0; it < 4; it++) {
            int k4 = lane + it * 32;
            float4 acc = ((const float4*)fc2)[n * 128 + k4];
#pragma unroll
            for (int s = 0; s < TT; s++) {
                float u = __shfl_sync(0xffffffffu, uval, s);
                float4 v = ((const float4*)g_h1A)[(b * TT + s) * 128 + k4];
                acc.x -= u * v.x; acc.y -= u * v.y; acc.z -= u * v.z; acc.w -= u * v.w;
            }
            ((float4*)g_w2)[(size_t)row * 128 + k4] = acc;
        }
    }
    // w3
    for (int row = gw; row < BB * HH; row += NW) {
        int b = row >> 9, n = row & 511;
        float uval = (lane < TT) ? lr * g_dz3A[(size_t)(b * TT + lane) * HH + n] : 0.f;
#pragma unroll
        for (int it = 0; it < 4; it++) {
            int k4 = lane + it * 32;
            float4 acc = ((const float4*)fc3)[n * 128 + k4];
#pragma unroll
            for (int s = 0; s < TT; s++) {
                float u = __shfl_sync(0xffffffffu, uval, s);
                float4 v = ((const float4*)g_h2A)[(b * TT + s) * 128 + k4];
                acc.x -= u * v.x; acc.y -= u * v.y; acc.z -= u * v.z; acc.w -= u * v.w;
            }
            ((float4*)g_w3)[(size_t)row * 128 + k4] = acc;
        }
    }
    // w4: rows BB*YY
    for (int row = gw; row < BB * YY; row += NW) {
        int b = row >> 8, n = row & 255;
        float uval = (lane < TT) ? lr * g_dlA[(size_t)(b * TT + lane) * YY + n] : 0.f;
#pragma unroll
        for (int it = 0; it < 4; it++) {
            int k4 = lane + it * 32;
            float4 acc = ((const float4*)fc4)[n * 128 + k4];
#pragma unroll
            for (int s = 0; s < TT; s++) {
                float u = __shfl_sync(0xffffffffu, uval, s);
                float4 v = ((const float4*)g_hgA)[(b * TT + s) * 128 + k4];
                acc.x -= u * v.x; acc.y -= u * v.y; acc.z -= u * v.z; acc.w -= u * v.w;
            }
            ((float4*)g_w4)[(size_t)row * 128 + k4] = acc;
        }
    }
}

// ---------------- eval: tiled GEMM with packed f32x2 FMA ----------------------
template <int LAYER>
__global__ void __launch_bounds__(256) k_eval(const float* __restrict__ extin,
                                              const float* __restrict__ gate,
                                              float* __restrict__ outp) {
    constexpr int N = (LAYER == 4) ? YY : HH;
    constexpr int K = (LAYER == 1) ? XX : HH;
    constexpr int NBLK = N / 128;
    __shared__ float Ws[32 * 130];
    __shared__ float Xs[64 * 33];
    int lb = blockIdx.x & 1;
    int tmp = blockIdx.x >> 1;
    int nb = tmp & (NBLK - 1);
    int b = tmp / NBLK;
    const float* W = (LAYER == 1) ? g_w1 : (LAYER == 2) ? g_w2 : (LAYER == 3) ? g_w3 : g_w4;
    const float* in = (LAYER == 1) ? extin : (LAYER == 2) ? g_ea : (LAYER == 3) ? g_eb : g_ea;
    const float* Wb = W + ((size_t)b * N + nb * 128) * K;
    const float* Ib = in + ((size_t)b * LL + lb * 64) * K;
    int tid = threadIdx.x;
    int tc = tid & 31, tr = tid >> 5;
    float2 acc[8][2];
#pragma unroll
    for (int i = 0; i < 8; i++) {
        acc[i][0] = make_float2(0.f, 0.f);
        acc[i][1] = make_float2(0.f, 0.f);
    }
    for (int kc = 0; kc < K; kc += 32) {
#pragma unroll
        for (int s = 0; s < 16; s++) {
            int e = tid + s * 256;
            int kk = e & 31, n = e >> 5;
            Ws[kk * 130 + n] = Wb[(size_t)n * K + kc + kk];
        }
#pragma unroll
        for (int s = 0; s < 8; s++) {
            int e = tid + s * 256;
            int kk = e & 31, l = e >> 5;
            Xs[l * 33 + kk] = Ib[(size_t)l * K + kc + kk];
        }
        __syncthreads();
#pragma unroll
        for (int kk = 0; kk < 32; kk++) {
            float2 w01 = *(const float2*)&Ws[kk * 130 + 2 * tc];
            float2 w23 = *(const float2*)&Ws[kk * 130 + 64 + 2 * tc];
#pragma unroll
            for (int i = 0; i < 8; i++) {
                float xv = Xs[(tr * 8 + i) * 33 + kk];
                float2 xx = make_float2(xv, xv);
                ffma2(acc[i][0], xx, w01);
                ffma2(acc[i][1], xx, w23);
            }
        }
        __syncthreads();
    }
    float2 bv0 = make_float2(0.f, 0.f), bv1 = make_float2(0.f, 0.f);
    if (LAYER != 4) {
        const float* bias = (LAYER == 1) ? g_b1 : (LAYER == 2) ? g_b2 : g_b3;
        bv0 = *(const float2*)&bias[b * HH + nb * 128 + 2 * tc];
        bv1 = *(const float2*)&bias[b * HH + nb * 128 + 64 + 2 * tc];
    }
    float* op = (LAYER == 4) ? outp : (LAYER == 1) ? g_ea : (LAYER == 2) ? g_eb : g_ea;
#pragma unroll
    for (int i = 0; i < 8; i++) {
        int l = lb * 64 + tr * 8 + i;
        size_t rowo = ((size_t)b * LL + l) * N + nb * 128;
        float2 v0 = acc[i][0], v1 = acc[i][1];
        if (LAYER != 4) {
            v0.x = fmaxf(v0.x + bv0.x, 0.f); v0.y = fmaxf(v0.y + bv0.y, 0.f);
            v1.x = fmaxf(v1.x + bv1.x, 0.f); v1.y = fmaxf(v1.y + bv1.y, 0.f);
        }
        if (LAYER == 3) {
            float2 gv0 = *(const float2*)&gate[((size_t)b * LL + l) * HH + nb * 128 + 2 * tc];
            float2 gv1 = *(const float2*)&gate[((size_t)b * LL + l) * HH + nb * 128 + 64 + 2 * tc];
            v0.x *= gv0.x; v0.y *= gv0.y; v1.x *= gv1.x; v1.y *= gv1.y;
        }
        if (LAYER == 4) {
            op[rowo + 2 * tc] = v0.x; op[rowo + 2 * tc + 1] = v0.y;
            op[rowo + 64 + 2 * tc] = v1.x; op[rowo + 64 + 2 * tc + 1] = v1.y;
        } else {
            *(float2*)&op[rowo + 2 * tc] = v0;
            *(float2*)&op[rowo + 64 + 2 * tc] = v1;
        }
    }
}

__global__ void k_loss(const float* __restrict__ ty, const float* __restrict__ loglr,
                       float* __restrict__ out) {
    int gw = (blockIdx.x * blockDim.x + threadIdx.x) >> 5;
    int lane = threadIdx.x & 31;
    if (gw >= BB * LL) return;
    const float* lg = out + 4097 + (size_t)gw * YY;
    const float* tyv = ty + (size_t)gw * YY;
    float acc = 0.f;
#pragma unroll
    for (int k = lane, it = 0; it < YY / 32; it++, k += 32) {
        float d = lg[k] - tyv[k];
        acc = fmaf(d, d, acc);
    }
    acc = warp_sum(acc);
    if (lane == 0) {
        float m = acc * (1.f / (float)YY);
        out[gw] = m;
        out[2049 + gw] = m;
    }
    if (gw == 0 && lane == 0) out[2048] = expf(*loglr);
}

extern "C" void kernel_launch(void* const* d_in, const int* in_sizes, int n_in,
                              void* d_out, int out_size) {
    const float* train_x = (const float*)d_in[0];
    const float* train_y = (const float*)d_in[1];
    const float* test_x = (const float*)d_in[2];
    const float* test_y = (const float*)d_in[3];
    const float* train_gate = (const float*)d_in[4];
    const float* test_gate = (const float*)d_in[5];
    const float* fc1 = (const float*)d_in[6];
    const float* b1 = (const float*)d_in[7];
    const float* fc2 = (const float*)d_in[8];
    const float* b2 = (const float*)d_in[9];
    const float* fc3 = (const float*)d_in[10];
    const float* b3 = (const float*)d_in[11];
    const float* fc4 = (const float*)d_in[12];
    const float* loglr = (const float*)d_in[13];
    float* out = (float*)d_out;

    k_tr<<<640, 256>>>(fc2, fc3, fc4);
    k_miscA<<<32, 256>>>(b1, b2, b3);
    k_miscB<<<64, 256>>>(train_x);
    k_train<<<64, TPB>>>(train_x, train_y, train_gate, fc1, fc2, fc3, fc4, loglr);
    k_material<<<1024, 256>>>(fc1, fc2, fc3, fc4, train_x, loglr);

    k_eval<1><<<BB * (HH / 128) * 2, 256>>>(test_x, nullptr, nullptr);
    k_eval<2><<<BB * (HH / 128) * 2, 256>>>(nullptr, nullptr, nullptr);
    k_eval<3><<<BB * (HH / 128) * 2, 256>>>(nullptr, test_gate, nullptr);
    k_eval<4><<<BB * (YY / 128) * 2, 256>>>(nullptr, nullptr, out + 4097);

    k_loss<<<256, 256>>>(test_y, loglr, out);
}

// round 6
// speedup vs baseline: 1.1432x; 1.1432x over previous
#include <cuda_runtime.h>
#include <math.h>
#include <stdint.h>

#define BB 16
#define TT 16
#define LL 128
#define XX 256
#define HH 512
#define YY 256
#define RCTA 8
#define TPB 512

__device__ __align__(16) float g_w1[BB * HH * XX];
__device__ __align__(16) float g_w2[BB * HH * HH];
__device__ __align__(16) float g_w3[BB * HH * HH];
__device__ __align__(16) float g_w4[BB * YY * HH];
__device__ __align__(16) float g_b1[BB * HH];
__device__ __align__(16) float g_b2[BB * HH];
__device__ __align__(16) float g_b3[BB * HH];
__device__ __align__(16) float g_w2T[HH * HH];
__device__ __align__(16) float g_w3T[HH * HH];
__device__ __align__(16) float g_w4T[HH * YY];
__device__ __align__(16) float g_h1A[BB * TT * HH];
__device__ __align__(16) float g_h2A[BB * TT * HH];
__device__ __align__(16) float g_h3A[BB * TT * HH];
__device__ __align__(16) float g_hgA[BB * TT * HH];
__device__ __align__(16) float g_dz1A[BB * TT * HH];
__device__ __align__(16) float g_dz2A[BB * TT * HH];
__device__ __align__(16) float g_dz3A[BB * TT * HH];
__device__ __align__(16) float g_dlA[BB * TT * YY];
__device__ __align__(16) float g_xg[BB * TT * TT];
__device__ __align__(16) float g_ea[BB * LL * HH];
__device__ __align__(16) float g_eb[BB * LL * HH];

__device__ __forceinline__ float warp_sum(float v) {
    v += __shfl_xor_sync(0xffffffffu, v, 16);
    v += __shfl_xor_sync(0xffffffffu, v, 8);
    v += __shfl_xor_sync(0xffffffffu, v, 4);
    v += __shfl_xor_sync(0xffffffffu, v, 2);
    v += __shfl_xor_sync(0xffffffffu, v, 1);
    return v;
}

__device__ __forceinline__ void csync() {
    asm volatile("barrier.cluster.arrive.aligned;" ::: "memory");
    asm volatile("barrier.cluster.wait.aligned;" ::: "memory");
}

__device__ __forceinline__ uint32_t s2u(const void* p) {
    return (uint32_t)__cvta_generic_to_shared(p);
}

// store float2 into the same smem offset of CTA `rank` in the cluster
__device__ __forceinline__ void st_cluster_f2(uint32_t saddr, int rank, float2 v) {
    uint32_t ra;
    unsigned long long u =
        ((unsigned long long)__float_as_uint(v.y) << 32) | __float_as_uint(v.x);
    asm volatile("mapa.shared::cluster.u32 %0, %1, %2;" : "=r"(ra) : "r"(saddr), "r"(rank));
    asm volatile("st.shared::cluster.b64 [%0], %1;" :: "r"(ra), "l"(u) : "memory");
}

// ---------------- pre-passes ----------------
__global__ void __launch_bounds__(256) k_tr(const float* __restrict__ fc2,
                                            const float* __restrict__ fc3,
                                            const float* __restrict__ fc4) {
    __shared__ float tile[32][33];
    int bid = blockIdx.x;
    const float* src;
    float* dst;
    int RS, CS;
    if (bid < 256) { src = fc2; dst = g_w2T; RS = HH; CS = HH; }
    else if (bid < 512) { src = fc3; dst = g_w3T; bid -= 256; RS = HH; CS = HH; }
    else { src = fc4; dst = g_w4T; bid -= 512; RS = YY; CS = HH; }
    int tpr = CS / 32;
    int r0 = (bid / tpr) * 32, c0 = (bid % tpr) * 32;
    int tx = threadIdx.x & 31, ty = threadIdx.x >> 5;
    for (int i = ty; i < 32; i += 8) tile[i][tx] = src[(size_t)(r0 + i) * CS + c0 + tx];
    __syncthreads();
    for (int i = ty; i < 32; i += 8) dst[(size_t)(c0 + i) * RS + r0 + tx] = tile[tx][i];
}

__global__ void __launch_bounds__(256) k_miscA(const float* __restrict__ b1,
                                               const float* __restrict__ b2,
                                               const float* __restrict__ b3) {
    int gt = blockIdx.x * blockDim.x + threadIdx.x;
    int NT = gridDim.x * blockDim.x;
    for (int i = gt; i < BB * HH; i += NT) {
        int k = i & (HH - 1);
        g_b1[i] = b1[k]; g_b2[i] = b2[k]; g_b3[i] = b3[k];
    }
}

__global__ void __launch_bounds__(256) k_miscB(const float* __restrict__ tx) {
    int gt = blockIdx.x * blockDim.x + threadIdx.x;
    int NT = gridDim.x * blockDim.x;
    int gw = gt >> 5, lane = gt & 31;
    for (int d = gw; d < BB * TT * TT; d += NT >> 5) {
        int b = d >> 8, s1 = (d >> 4) & 15, s2 = d & 15;
        const float4* xa = (const float4*)(tx + (size_t)(b * TT + s1) * XX);
        const float4* xb = (const float4*)(tx + (size_t)(b * TT + s2) * XX);
        float4 a = xa[lane], c = xb[lane];
        float acc = a.x * c.x + a.y * c.y + a.z * c.z + a.w * c.w;
        a = xa[lane + 32]; c = xb[lane + 32];
        acc += a.x * c.x + a.y * c.y + a.z * c.z + a.w * c.w;
        acc = warp_sum(acc);
        if (lane == 0) g_xg[d] = acc;
    }
}

// ---------------- train building blocks ----------------
// octet (8 lanes) matvec: W row n vs smem vector (float2 = both examples)
template <int K>
__device__ __forceinline__ float2 omv_s(const float* __restrict__ W, int n,
                                        const float2* __restrict__ sv, int l8) {
    const float4* w4 = (const float4*)(W + (size_t)n * K);
    const float4* v4 = (const float4*)sv;
    float a0 = 0.f, a1 = 0.f, c0 = 0.f, c1 = 0.f;
#pragma unroll
    for (int jj = 0; jj < K / 32; jj++) {
        int j = l8 + jj * 8;
        float4 w = w4[j];
        float4 p = v4[2 * j], q = v4[2 * j + 1];
        a0 = fmaf(w.x, p.x, a0); a1 = fmaf(w.x, p.y, a1);
        c0 = fmaf(w.y, p.z, c0); c1 = fmaf(w.y, p.w, c1);
        a0 = fmaf(w.z, q.x, a0); a1 = fmaf(w.z, q.y, a1);
        c0 = fmaf(w.w, q.z, c0); c1 = fmaf(w.w, q.w, c1);
    }
    return make_float2(a0 + c0, a1 + c1);
}

__device__ __forceinline__ void ored2(float2& a) {
#pragma unroll
    for (int m = 1; m < 8; m <<= 1) {
        a.x += __shfl_xor_sync(0xffffffffu, a.x, m);
        a.y += __shfl_xor_sync(0xffffffffu, a.y, m);
    }
}

// low-rank correction: a -= sum_{s<t} c[2s+b] * uA[b][s][n]  (u's are own-CTA writes)
template <int NU>
__device__ __forceinline__ void corr2(const float* __restrict__ uA, int b0, int n,
                                      const float* s_c, int t, int l8, float2& a) {
#pragma unroll
    for (int ss = 0; ss < 2; ss++) {
        int s = l8 + ss * 8;
        if (s < t) {
            float u0 = uA[(size_t)(b0 * TT + s) * NU + n];
            float u1 = uA[(size_t)((b0 + 1) * TT + s) * NU + n];
            a.x = fmaf(-s_c[2 * s], u0, a.x);
            a.y = fmaf(-s_c[2 * s + 1], u1, a.y);
        }
    }
}

// sum 8 per-rank partials -> lr-scaled coefficients
__device__ __forceinline__ void sumc(const float (*sp)[32], float* s_c, int tid, float lr) {
    if (tid < 32) {
        float s = 0.f;
#pragma unroll
        for (int rr = 0; rr < RCTA; rr++) s += sp[rr][tid];
        s_c[tid] = lr * s;
    }
    __syncthreads();
}

// after producing chunk values (in s_new): broadcast to peers' next-parity vector
// buffer, and compute partial dots vs own history slice -> peers' partial buffer.
template <int NPC, int KD>
__device__ __forceinline__ void publish(float2* dst_vec, float* dst_part,
                                        const float2* s_new,
                                        const float* __restrict__ histA,
                                        int b0, int r, int t, int tid) {
    __syncthreads();
    if (tid < NPC) {
        float2 v = s_new[tid];
        uint32_t sa = s2u(&dst_vec[r * NPC + tid]);
#pragma unroll
        for (int rr = 0; rr < RCTA; rr++) st_cluster_f2(sa, rr, v);
    }
    int w = tid >> 5, lane = tid & 31;
    if (w < t) {
        float a0 = 0.f, a1 = 0.f;
#pragma unroll
        for (int ii = 0; ii < NPC / 32; ii++) {
            int i = lane + 32 * ii;
            float2 nv = s_new[i];
            float h0 = histA[(size_t)(b0 * TT + w) * KD + r * NPC + i];
            float h1 = histA[(size_t)((b0 + 1) * TT + w) * KD + r * NPC + i];
            a0 = fmaf(h0, nv.x, a0);
            a1 = fmaf(h1, nv.y, a1);
        }
        a0 = warp_sum(a0); a1 = warp_sum(a1);
        if (lane == 0) {
            uint32_t sa = s2u(&dst_part[r * 32 + 2 * w]);
            float2 pv = make_float2(a0, a1);
#pragma unroll
            for (int rr = 0; rr < RCTA; rr++) st_cluster_f2(sa, rr, pv);
        }
    }
}

// ---------------- training: 8 clusters x 8 CTAs, 2 examples/cluster ----------
__global__ void __cluster_dims__(RCTA, 1, 1) __launch_bounds__(TPB, 1)
k_train(const float* __restrict__ tx, const float* __restrict__ ty,
        const float* __restrict__ tg,
        const float* __restrict__ fc1, const float* __restrict__ fc2,
        const float* __restrict__ fc3, const float* __restrict__ fc4,
        const float* __restrict__ loglr) {
    __shared__ __align__(16) float2 s_vec[2][HH];
    __shared__ __align__(16) float s_part[2][RCTA][32];
    __shared__ __align__(16) float2 s_new[64];
    __shared__ float s_c[32];
    int tid = threadIdx.x;
    int r = blockIdx.x & (RCTA - 1);
    int b0 = (blockIdx.x / RCTA) * 2;
    int l8 = tid & 7;
    int oct = tid >> 3;
    float lr = expf(*loglr);

    for (int t = 0; t < TT; t++) {
        // ======== fwd1 (par=0): local vector fill, gram coefficients ========
        {
            const float* x0 = tx + (size_t)(b0 * TT + t) * XX;
            const float* x1 = tx + (size_t)((b0 + 1) * TT + t) * XX;
            for (int k = tid; k < XX; k += TPB)
                s_vec[0][k] = make_float2(x0[k], x1[k]);
            if (tid < 32) {
                int s = tid >> 1, bsel = tid & 1;
                s_c[tid] = (s < t) ? lr * g_xg[((b0 + bsel) * TT + s) * TT + t] : 0.f;
            }
            __syncthreads();
            int n = r * 64 + oct;
            float2 a = omv_s<XX>(fc1, n, s_vec[0], l8);
            corr2<HH>(g_dz1A, b0, n, s_c, t, l8, a);
            ored2(a);
            if (l8 == 0) {
                float h0 = fmaxf(a.x + g_b1[b0 * HH + n], 0.f);
                float h1 = fmaxf(a.y + g_b1[(b0 + 1) * HH + n], 0.f);
                g_h1A[(size_t)(b0 * TT + t) * HH + n] = h0;
                g_h1A[(size_t)((b0 + 1) * TT + t) * HH + n] = h1;
                s_new[oct] = make_float2(h0, h1);
            }
            publish<64, HH>(s_vec[1], &s_part[1][0][0], s_new, g_h1A, b0, r, t, tid);
            csync();
        }
        // ======== fwd2 (par=1) ========
        {
            sumc(s_part[1], s_c, tid, lr);
            int n = r * 64 + oct;
            float2 a = omv_s<HH>(fc2, n, s_vec[1], l8);
            corr2<HH>(g_dz2A, b0, n, s_c, t, l8, a);
            ored2(a);
            if (l8 == 0) {
                float h0 = fmaxf(a.x + g_b2[b0 * HH + n], 0.f);
                float h1 = fmaxf(a.y + g_b2[(b0 + 1) * HH + n], 0.f);
                g_h2A[(size_t)(b0 * TT + t) * HH + n] = h0;
                g_h2A[(size_t)((b0 + 1) * TT + t) * HH + n] = h1;
                s_new[oct] = make_float2(h0, h1);
            }
            publish<64, HH>(s_vec[0], &s_part[0][0][0], s_new, g_h2A, b0, r, t, tid);
            csync();
        }
        // ======== fwd3 + gate (par=0) ========
        {
            sumc(s_part[0], s_c, tid, lr);
            int n = r * 64 + oct;
            float2 a = omv_s<HH>(fc3, n, s_vec[0], l8);
            corr2<HH>(g_dz3A, b0, n, s_c, t, l8, a);
            ored2(a);
            if (l8 == 0) {
                float h30 = fmaxf(a.x + g_b3[b0 * HH + n], 0.f);
                float h31 = fmaxf(a.y + g_b3[(b0 + 1) * HH + n], 0.f);
                g_h3A[(size_t)(b0 * TT + t) * HH + n] = h30;
                g_h3A[(size_t)((b0 + 1) * TT + t) * HH + n] = h31;
                float hg0 = h30 * tg[(size_t)(b0 * TT + t) * HH + n];
                float hg1 = h31 * tg[(size_t)((b0 + 1) * TT + t) * HH + n];
                g_hgA[(size_t)(b0 * TT + t) * HH + n] = hg0;
                g_hgA[(size_t)((b0 + 1) * TT + t) * HH + n] = hg1;
                s_new[oct] = make_float2(hg0, hg1);
            }
            publish<64, HH>(s_vec[1], &s_part[1][0][0], s_new, g_hgA, b0, r, t, tid);
            csync();
        }
        // ======== fwd4 -> dlogit (par=1) ========
        {
            sumc(s_part[1], s_c, tid, lr);
            if (oct < 32) {
                int n = r * 32 + oct;
                float2 a = omv_s<HH>(fc4, n, s_vec[1], l8);
                corr2<YY>(g_dlA, b0, n, s_c, t, l8, a);
                ored2(a);
                if (l8 == 0) {
                    float d0 = (2.f / (float)YY) * (a.x - ty[(size_t)(b0 * TT + t) * YY + n]);
                    float d1 = (2.f / (float)YY) * (a.y - ty[(size_t)((b0 + 1) * TT + t) * YY + n]);
                    g_dlA[(size_t)(b0 * TT + t) * YY + n] = d0;
                    g_dlA[(size_t)((b0 + 1) * TT + t) * YY + n] = d1;
                    s_new[oct] = make_float2(d0, d1);
                }
            }
            publish<32, YY>(s_vec[0], &s_part[0][0][0], s_new, g_dlA, b0, r, t, tid);
            csync();
        }
        // ======== bwd4: dhg -> dz3, b3 update (par=0) ========
        {
            sumc(s_part[0], s_c, tid, lr);
            int n = r * 64 + oct;
            float2 a = omv_s<YY>(g_w4T, n, s_vec[0], l8);
            corr2<HH>(g_hgA, b0, n, s_c, t, l8, a);
            ored2(a);
            if (l8 == 0) {
                float h30 = g_h3A[(size_t)(b0 * TT + t) * HH + n];
                float h31 = g_h3A[(size_t)((b0 + 1) * TT + t) * HH + n];
                float d0 = (h30 > 0.f) ? a.x * tg[(size_t)(b0 * TT + t) * HH + n] : 0.f;
                float d1 = (h31 > 0.f) ? a.y * tg[(size_t)((b0 + 1) * TT + t) * HH + n] : 0.f;
                g_dz3A[(size_t)(b0 * TT + t) * HH + n] = d0;
                g_dz3A[(size_t)((b0 + 1) * TT + t) * HH + n] = d1;
                g_b3[b0 * HH + n] -= lr * d0;
                g_b3[(b0 + 1) * HH + n] -= lr * d1;
                s_new[oct] = make_float2(d0, d1);
            }
            publish<64, HH>(s_vec[1], &s_part[1][0][0], s_new, g_dz3A, b0, r, t, tid);
            csync();
        }
        // ======== bwd3: dh2 -> dz2, b2 update (par=1) ========
        {
            sumc(s_part[1], s_c, tid, lr);
            int n = r * 64 + oct;
            float2 a = omv_s<HH>(g_w3T, n, s_vec[1], l8);
            corr2<HH>(g_h2A, b0, n, s_c, t, l8, a);
            ored2(a);
            if (l8 == 0) {
                float h20 = g_h2A[(size_t)(b0 * TT + t) * HH + n];
                float h21 = g_h2A[(size_t)((b0 + 1) * TT + t) * HH + n];
                float d0 = (h20 > 0.f) ? a.x : 0.f;
                float d1 = (h21 > 0.f) ? a.y : 0.f;
                g_dz2A[(size_t)(b0 * TT + t) * HH + n] = d0;
                g_dz2A[(size_t)((b0 + 1) * TT + t) * HH + n] = d1;
                g_b2[b0 * HH + n] -= lr * d0;
                g_b2[(b0 + 1) * HH + n] -= lr * d1;
                s_new[oct] = make_float2(d0, d1);
            }
            publish<64, HH>(s_vec[0], &s_part[0][0][0], s_new, g_dz2A, b0, r, t, tid);
            csync();
        }
        // ======== bwd2: dh1 -> dz1, b1 update (par=0, no publish/barrier) ====
        {
            sumc(s_part[0], s_c, tid, lr);
            int n = r * 64 + oct;
            float2 a = omv_s<HH>(g_w2T, n, s_vec[0], l8);
            corr2<HH>(g_h1A, b0, n, s_c, t, l8, a);
            ored2(a);
            if (l8 == 0) {
                float h10 = g_h1A[(size_t)(b0 * TT + t) * HH + n];
                float h11 = g_h1A[(size_t)((b0 + 1) * TT + t) * HH + n];
                float d0 = (h10 > 0.f) ? a.x : 0.f;
                float d1 = (h11 > 0.f) ? a.y : 0.f;
                g_dz1A[(size_t)(b0 * TT + t) * HH + n] = d0;
                g_dz1A[(size_t)((b0 + 1) * TT + t) * HH + n] = d1;
                g_b1[b0 * HH + n] -= lr * d0;
                g_b1[(b0 + 1) * HH + n] -= lr * d1;
            }
            __syncthreads();  // protect s_vec[0]/s_c before fwd1(t+1) refills
        }
    }
}

// ---------------- materialize: warp-per-row rank-16 --------------------------
__global__ void __launch_bounds__(256) k_material(
    const float* __restrict__ fc1, const float* __restrict__ fc2,
    const float* __restrict__ fc3, const float* __restrict__ fc4,
    const float* __restrict__ tx, const float* __restrict__ loglr) {
    float lr = expf(*loglr);
    int gw = (blockIdx.x * blockDim.x + threadIdx.x) >> 5;
    int lane = threadIdx.x & 31;
    int NW = (gridDim.x * blockDim.x) >> 5;
    for (int row = gw; row < BB * HH; row += NW) {
        int b = row >> 9, n = row & 511;
        float uval = (lane < TT) ? lr * g_dz1A[(size_t)(b * TT + lane) * HH + n] : 0.f;
#pragma unroll
        for (int it = 0; it < 2; it++) {
            int k4 = lane + it * 32;
            float4 acc = ((const float4*)fc1)[n * 64 + k4];
#pragma unroll
            for (int s = 0; s < TT; s++) {
                float u = __shfl_sync(0xffffffffu, uval, s);
                float4 v = ((const float4*)tx)[(b * TT + s) * 64 + k4];
                acc.x -= u * v.x; acc.y -= u * v.y; acc.z -= u * v.z; acc.w -= u * v.w;
            }
            ((float4*)g_w1)[(size_t)row * 64 + k4] = acc;
        }
    }
    for (int row = gw; row < BB * HH; row += NW) {
        int b = row >> 9, n = row & 511;
        float uval = (lane < TT) ? lr * g_dz2A[(size_t)(b * TT + lane) * HH + n] : 0.f;
#pragma unroll
        for (int it = 0; it < 4; it++) {
            int k4 = lane + it * 32;
            float4 acc = ((const float4*)fc2)[n * 128 + k4];
#pragma unroll
            for (int s = 0; s < TT; s++) {
                float u = __shfl_sync(0xffffffffu, uval, s);
                float4 v = ((const float4*)g_h1A)[(b * TT + s) * 128 + k4];
                acc.x -= u * v.x; acc.y -= u * v.y; acc.z -= u * v.z; acc.w -= u * v.w;
            }
            ((float4*)g_w2)[(size_t)row * 128 + k4] = acc;
        }
    }
    for (int row = gw; row < BB * HH; row += NW) {
        int b = row >> 9, n = row & 511;
        float uval = (lane < TT) ? lr * g_dz3A[(size_t)(b * TT + lane) * HH + n] : 0.f;
#pragma unroll
        for (int it = 0; it < 4; it++) {
            int k4 = lane + it * 32;
            float4 acc = ((const float4*)fc3)[n * 128 + k4];
#pragma unroll
            for (int s = 0; s < TT; s++) {
                float u = __shfl_sync(0xffffffffu, uval, s);
                float4 v = ((const float4*)g_h2A)[(b * TT + s) * 128 + k4];
                acc.x -= u * v.x; acc.y -= u * v.y; acc.z -= u * v.z; acc.w -= u * v.w;
            }
            ((float4*)g_w3)[(size_t)row * 128 + k4] = acc;
        }
    }
    for (int row = gw; row < BB * YY; row += NW) {
        int b = row >> 8, n = row & 255;
        float uval = (lane < TT) ? lr * g_dlA[(size_t)(b * TT + lane) * YY + n] : 0.f;
#pragma unroll
        for (int it = 0; it < 4; it++) {
            int k4 = lane + it * 32;
            float4 acc = ((const float4*)fc4)[n * 128 + k4];
#pragma unroll
            for (int s = 0; s < TT; s++) {
                float u = __shfl_sync(0xffffffffu, uval, s);
                float4 v = ((const float4*)g_hgA)[(b * TT + s) * 128 + k4];
                acc.x -= u * v.x; acc.y -= u * v.y; acc.z -= u * v.z; acc.w -= u * v.w;
            }
            ((float4*)g_w4)[(size_t)row * 128 + k4] = acc;
        }
    }
}

// ---------------- eval: tiled fp32 GEMM (proven R1/R4 form) -------------------
template <int LAYER>
__global__ void __launch_bounds__(256) k_eval(const float* __restrict__ extin,
                                              const float* __restrict__ gate,
                                              float* __restrict__ outp) {
    constexpr int N = (LAYER == 4) ? YY : HH;
    constexpr int K = (LAYER == 1) ? XX : HH;
    constexpr int NBLK = N / 128;
    __shared__ float Ws[32 * 129];
    __shared__ float Xs[64 * 33];
    int lb = blockIdx.x & 1;
    int tmp = blockIdx.x >> 1;
    int nb = tmp & (NBLK - 1);
    int b = tmp / NBLK;
    const float* W = (LAYER == 1) ? g_w1 : (LAYER == 2) ? g_w2 : (LAYER == 3) ? g_w3 : g_w4;
    const float* in = (LAYER == 1) ? extin : (LAYER == 2) ? g_ea : (LAYER == 3) ? g_eb : g_ea;
    const float* Wb = W + ((size_t)b * N + nb * 128) * K;
    const float* Ib = in + ((size_t)b * LL + lb * 64) * K;
    int tid = threadIdx.x;
    int tc = tid & 31, tr = tid >> 5;
    float acc[8][4];
#pragma unroll
    for (int i = 0; i < 8; i++)
#pragma unroll
        for (int d = 0; d < 4; d++) acc[i][d] = 0.f;
    for (int kc = 0; kc < K; kc += 32) {
#pragma unroll
        for (int s = 0; s < 16; s++) {
            int e = tid + s * 256;
            int kk = e & 31, n = e >> 5;
            Ws[kk * 129 + n] = Wb[(size_t)n * K + kc + kk];
        }
#pragma unroll
        for (int s = 0; s < 8; s++) {
            int e = tid + s * 256;
            int kk = e & 31, l = e >> 5;
            Xs[l * 33 + kk] = Ib[(size_t)l * K + kc + kk];
        }
        __syncthreads();
#pragma unroll
        for (int kk = 0; kk < 32; kk++) {
            float w0 = Ws[kk * 129 + tc];
            float w1 = Ws[kk * 129 + tc + 32];
            float w2 = Ws[kk * 129 + tc + 64];
            float w3 = Ws[kk * 129 + tc + 96];
#pragma unroll
            for (int i = 0; i < 8; i++) {
                float xv = Xs[(tr * 8 + i) * 33 + kk];
                acc[i][0] = fmaf(xv, w0, acc[i][0]);
                acc[i][1] = fmaf(xv, w1, acc[i][1]);
                acc[i][2] = fmaf(xv, w2, acc[i][2]);
                acc[i][3] = fmaf(xv, w3, acc[i][3]);
            }
        }
        __syncthreads();
    }
    float bv[4] = {0.f, 0.f, 0.f, 0.f};
    if (LAYER != 4) {
        const float* bias = (LAYER == 1) ? g_b1 : (LAYER == 2) ? g_b2 : g_b3;
#pragma unroll
        for (int d = 0; d < 4; d++) bv[d] = bias[b * HH + nb * 128 + tc + 32 * d];
    }
    float* op = (LAYER == 4) ? outp : (LAYER == 1) ? g_ea : (LAYER == 2) ? g_eb : g_ea;
#pragma unroll
    for (int i = 0; i < 8; i++) {
        int l = lb * 64 + tr * 8 + i;
        size_t rowo = ((size_t)b * LL + l) * N + nb * 128;
#pragma unroll
        for (int d = 0; d < 4; d++) {
            float v = acc[i][d];
            if (LAYER != 4) v = fmaxf(v + bv[d], 0.f);
            if (LAYER == 3) v *= gate[((size_t)b * LL + l) * HH + nb * 128 + tc + 32 * d];
            op[rowo + tc + 32 * d] = v;
        }
    }
}

__global__ void k_loss(const float* __restrict__ ty, const float* __restrict__ loglr,
                       float* __restrict__ out) {
    int gw = (blockIdx.x * blockDim.x + threadIdx.x) >> 5;
    int lane = threadIdx.x & 31;
    if (gw >= BB * LL) return;
    const float* lg = out + 4097 + (size_t)gw * YY;
    const float* tyv = ty + (size_t)gw * YY;
    float acc = 0.f;
#pragma unroll
    for (int k = lane, it = 0; it < YY / 32; it++, k += 32) {
        float d = lg[k] - tyv[k];
        acc = fmaf(d, d, acc);
    }
    acc = warp_sum(acc);
    if (lane == 0) {
        float m = acc * (1.f / (float)YY);
        out[gw] = m;
        out[2049 + gw] = m;
    }
    if (gw == 0 && lane == 0) out[2048] = expf(*loglr);
}

extern "C" void kernel_launch(void* const* d_in, const int* in_sizes, int n_in,
                              void* d_out, int out_size) {
    const float* train_x = (const float*)d_in[0];
    const float* train_y = (const float*)d_in[1];
    const float* test_x = (const float*)d_in[2];
    const float* test_y = (const float*)d_in[3];
    const float* train_gate = (const float*)d_in[4];
    const float* test_gate = (const float*)d_in[5];
    const float* fc1 = (const float*)d_in[6];
    const float* b1 = (const float*)d_in[7];
    const float* fc2 = (const float*)d_in[8];
    const float* b2 = (const float*)d_in[9];
    const float* fc3 = (const float*)d_in[10];
    const float* b3 = (const float*)d_in[11];
    const float* fc4 = (const float*)d_in[12];
    const float* loglr = (const float*)d_in[13];
    float* out = (float*)d_out;

    k_tr<<<640, 256>>>(fc2, fc3, fc4);
    k_miscA<<<32, 256>>>(b1, b2, b3);
    k_miscB<<<64, 256>>>(train_x);
    k_train<<<64, TPB>>>(train_x, train_y, train_gate, fc1, fc2, fc3, fc4, loglr);
    k_material<<<1024, 256>>>(fc1, fc2, fc3, fc4, train_x, loglr);

    k_eval<1><<<BB * (HH / 128) * 2, 256>>>(test_x, nullptr, nullptr);
    k_eval<2><<<BB * (HH / 128) * 2, 256>>>(nullptr, nullptr, nullptr);
    k_eval<3><<<BB * (HH / 128) * 2, 256>>>(nullptr, test_gate, nullptr);
    k_eval<4><<<BB * (YY / 128) * 2, 256>>>(nullptr, nullptr, out + 4097);

    k_loss<<<256, 256>>>(test_y, loglr, out);
}